// round 2
// baseline (speedup 1.0000x reference)
#include <cuda_runtime.h>
#include <cuda_bf16.h>
#include <math.h>

#define Pn 7
#define Sn 4
#define SCALE 0.0625f
#define TRANS_STD 0.1f
#define Cc 128
#define DF 1024
#define Bb 2
#define Hh 160
#define Ww 160
#define Nroi 256
#define INF (Cc*Pn*Pn)   // 6272
#define HW (Hh*Ww)       // 25600

// ---------------- scratch (static device allocations; no cudaMalloc) ----------------
__device__ float g_dataT[Bb*HW*Cc];        // (B,H,W,C) transposed data
__device__ float g_x[Nroi*INF];            // pooled features, (N, C*P*P)
__device__ float g_part[8*Nroi*DF];        // split-K partials (8 z-slices of 256x1024)
__device__ float g_h1[Nroi*DF];
__device__ float g_m1[Nroi*DF];
__device__ float g_h2[Nroi*DF];
__device__ float g_off[Nroi*2*Pn*Pn];      // offsets (N,2,7,7)
__device__ float g_mask[Nroi*Pn*Pn];       // mask (N,7,7)

// ---------------- transpose (B,C,H,W) -> (B,H,W,C) ----------------
__global__ void transpose_kernel(const float* __restrict__ in) {
    __shared__ float tile[32][33];
    int b  = blockIdx.z;
    int p0 = blockIdx.x * 32;
    int c0 = blockIdx.y * 32;
    int tx = threadIdx.x, ty = threadIdx.y;
    const float* src = in + (size_t)b * Cc * HW;
    float* dst = g_dataT + (size_t)b * HW * Cc;
    #pragma unroll
    for (int i = 0; i < 4; i++)
        tile[ty + 8*i][tx] = src[(c0 + ty + 8*i) * HW + p0 + tx];
    __syncthreads();
    #pragma unroll
    for (int i = 0; i < 4; i++)
        dst[(p0 + ty + 8*i) * Cc + c0 + tx] = tile[tx][ty + 8*i];
}

// ---------------- deformable RoI pool ----------------
// grid (Nroi, P), block 128 (one thread per channel)
// TRANS=false: write g_x. TRANS=true: apply offsets, multiply mask, write out.
template<bool TRANS>
__global__ __launch_bounds__(128) void pool_kernel(
    const float* __restrict__ rois,
    const float* __restrict__ trans,   // (N,2,7,7) or null
    const float* __restrict__ mask,    // (N,7,7) or null
    float* __restrict__ out)
{
    int n  = blockIdx.x;
    int ph = blockIdx.y;
    int c  = threadIdx.x;

    const float* r = rois + n * 5;
    int   bi = (int)r[0];
    float x1 = rintf(r[1]) * SCALE - 0.5f;
    float y1 = rintf(r[2]) * SCALE - 0.5f;
    float x2 = (rintf(r[3]) + 1.0f) * SCALE - 0.5f;
    float y2 = (rintf(r[4]) + 1.0f) * SCALE - 0.5f;
    float roi_w = fmaxf(x2 - x1, 0.1f);
    float roi_h = fmaxf(y2 - y1, 0.1f);
    float bin_w = roi_w / (float)Pn;
    float bin_h = roi_h / (float)Pn;
    float sub_w = bin_w / (float)Sn;
    float sub_h = bin_h / (float)Sn;

    const float* base = g_dataT + (size_t)bi * HW * Cc;

    for (int pw = 0; pw < Pn; pw++) {
        float tx = 0.f, tyv = 0.f;
        if (TRANS) {
            tx  = trans[n*98 +      ph*7 + pw] * TRANS_STD;
            tyv = trans[n*98 + 49 + ph*7 + pw] * TRANS_STD;
        }
        float wst = (float)pw * bin_w + x1 + tx  * roi_w;
        float hst = (float)ph * bin_h + y1 + tyv * roi_h;

        float acc = 0.f;
        int cnt = 0;
        #pragma unroll
        for (int ih = 0; ih < Sn; ih++) {
            float hv = hst + (float)ih * sub_h;
            #pragma unroll
            for (int iw = 0; iw < Sn; iw++) {
                float wv = wst + (float)iw * sub_w;
                if (wv < -0.5f || wv > (float)Ww - 0.5f ||
                    hv < -0.5f || hv > (float)Hh - 0.5f) continue;
                float wc = fminf(fmaxf(wv, 0.f), (float)Ww - 1.f);
                float hc = fminf(fmaxf(hv, 0.f), (float)Hh - 1.f);
                int x0 = (int)floorf(wc);
                int y0 = (int)floorf(hc);
                int x1i = min(x0 + 1, Ww - 1);
                int y1i = min(y0 + 1, Hh - 1);
                float lx = wc - (float)x0;
                float ly = hc - (float)y0;
                const float* p00 = base + (y0  * Ww + x0 ) * Cc;
                const float* p01 = base + (y0  * Ww + x1i) * Cc;
                const float* p10 = base + (y1i * Ww + x0 ) * Cc;
                const float* p11 = base + (y1i * Ww + x1i) * Cc;
                float v = p00[c] * ((1.f-ly)*(1.f-lx))
                        + p01[c] * ((1.f-ly)*lx)
                        + p10[c] * (ly*(1.f-lx))
                        + p11[c] * (ly*lx);
                acc += v;
                cnt++;
            }
        }
        float res = (cnt > 0) ? acc / (float)cnt : 0.f;
        if (TRANS) res *= mask[n*49 + ph*7 + pw];
        out[n*INF + c*49 + ph*7 + pw] = res;   // (N,C,P,P) linearized
    }
}

// ---------------- big GEMM: 128x128 tile, 8x8 per thread, split-K partials --------
// grid: (Ntiles=N/128, Mtiles=M/128, z) ; z -> wsel = z/kspl, kchunk = z%kspl
// partials written to g_part[z][m][1024-wide n]
__global__ __launch_bounds__(256) void gemm128(
    const float* __restrict__ A, int lda,
    const float* __restrict__ B0, const float* __restrict__ B1, int ldb,
    float* __restrict__ part, int klen, int kspl)
{
    __shared__ float As[8][128];
    __shared__ float Bs[8][128];

    int z = blockIdx.z;
    const float* B = (z / kspl == 0) ? B0 : B1;
    int kbase = (z % kspl) * klen;

    int tid = threadIdx.x;
    int a_r = tid >> 1;          // 0..127
    int a_c = (tid & 1) * 4;     // 0 or 4
    int b_r = tid >> 5;          // 0..7
    int b_c = (tid & 31) * 4;    // 0..124

    const float* Ap = A + (size_t)(blockIdx.y * 128 + a_r) * lda + kbase + a_c;
    const float* Bp = B + (size_t)(kbase + b_r) * ldb + blockIdx.x * 128 + b_c;

    int tx = tid & 15;           // 0..15
    int ty = tid >> 4;           // 0..15

    float acc[8][8];
    #pragma unroll
    for (int i = 0; i < 8; i++)
        #pragma unroll
        for (int j = 0; j < 8; j++) acc[i][j] = 0.f;

    int stages = klen / 8;
    float4 pa = *(const float4*)Ap;
    float4 pb = *(const float4*)Bp;

    for (int s = 0; s < stages; s++) {
        As[a_c + 0][a_r] = pa.x;
        As[a_c + 1][a_r] = pa.y;
        As[a_c + 2][a_r] = pa.z;
        As[a_c + 3][a_r] = pa.w;
        *(float4*)&Bs[b_r][b_c] = pb;
        __syncthreads();

        Ap += 8;
        Bp += (size_t)8 * ldb;
        if (s + 1 < stages) {
            pa = *(const float4*)Ap;
            pb = *(const float4*)Bp;
        }

        #pragma unroll
        for (int kk = 0; kk < 8; kk++) {
            float4 a0 = *(const float4*)&As[kk][ty * 4];
            float4 a1 = *(const float4*)&As[kk][64 + ty * 4];
            float4 b0 = *(const float4*)&Bs[kk][tx * 4];
            float4 b1 = *(const float4*)&Bs[kk][64 + tx * 4];
            float av[8] = {a0.x,a0.y,a0.z,a0.w,a1.x,a1.y,a1.z,a1.w};
            float bv[8] = {b0.x,b0.y,b0.z,b0.w,b1.x,b1.y,b1.z,b1.w};
            #pragma unroll
            for (int i = 0; i < 8; i++)
                #pragma unroll
                for (int j = 0; j < 8; j++)
                    acc[i][j] += av[i] * bv[j];
        }
        __syncthreads();
    }

    float* Cp = part + ((size_t)z * Nroi + blockIdx.y * 128) * DF + blockIdx.x * 128;
    #pragma unroll
    for (int i = 0; i < 8; i++) {
        int rr = (i < 4) ? (ty * 4 + i) : (64 + ty * 4 + i - 4);
        float4 v0 = make_float4(acc[i][0], acc[i][1], acc[i][2], acc[i][3]);
        float4 v1 = make_float4(acc[i][4], acc[i][5], acc[i][6], acc[i][7]);
        *(float4*)&Cp[(size_t)rr * DF + tx * 4]      = v0;
        *(float4*)&Cp[(size_t)rr * DF + 64 + tx * 4] = v1;
    }
}

// reduce 4 partials each for h1 (z=0..3, bias b1) and m1 (z=4..7, bias bm1), relu
__global__ void reduce1_kernel(const float* __restrict__ b1, const float* __restrict__ bm1) {
    int i = blockIdx.x * 256 + threadIdx.x;   // over 256*1024
    int n = i & (DF - 1);
    float s0 = b1[n], s1 = bm1[n];
    #pragma unroll
    for (int c = 0; c < 4; c++) s0 += g_part[(size_t)c * (Nroi*DF) + i];
    #pragma unroll
    for (int c = 4; c < 8; c++) s1 += g_part[(size_t)c * (Nroi*DF) + i];
    g_h1[i] = fmaxf(s0, 0.f);
    g_m1[i] = fmaxf(s1, 0.f);
}

// reduce 8 partials for h2, bias b2, relu
__global__ void reduce2_kernel(const float* __restrict__ b2) {
    int i = blockIdx.x * 256 + threadIdx.x;
    int n = i & (DF - 1);
    float s = b2[n];
    #pragma unroll
    for (int c = 0; c < 8; c++) s += g_part[(size_t)c * (Nroi*DF) + i];
    g_h2[i] = fmaxf(s, 0.f);
}

// ---------------- small GEMM: (256,1024) @ (1024,Ncols) + bias [, sigmoid] -------
// grid 32 blocks (8 rows each), 128 threads (one per output col, Ncols<=128)
__global__ __launch_bounds__(128) void gemm_small(
    const float* __restrict__ A, const float* __restrict__ Wt,
    const float* __restrict__ bias, float* __restrict__ out,
    int Ncols, int act)
{
    __shared__ float arow[8][DF];
    int tid = threadIdx.x;
    int m0 = blockIdx.x * 8;
    #pragma unroll
    for (int g = 0; g < 8; g++)
        for (int k = tid; k < DF; k += 128)
            arow[g][k] = A[(size_t)(m0 + g) * DF + k];
    __syncthreads();

    if (tid < Ncols) {
        float bv = bias[tid];
        float acc[8];
        #pragma unroll
        for (int g = 0; g < 8; g++) acc[g] = bv;
        for (int k = 0; k < DF; k += 4) {
            float w0 = Wt[(size_t)(k + 0) * Ncols + tid];
            float w1 = Wt[(size_t)(k + 1) * Ncols + tid];
            float w2 = Wt[(size_t)(k + 2) * Ncols + tid];
            float w3 = Wt[(size_t)(k + 3) * Ncols + tid];
            #pragma unroll
            for (int g = 0; g < 8; g++) {
                float4 av = *(const float4*)&arow[g][k];
                acc[g] += av.x * w0 + av.y * w1 + av.z * w2 + av.w * w3;
            }
        }
        #pragma unroll
        for (int g = 0; g < 8; g++) {
            float v = acc[g];
            if (act) v = 1.f / (1.f + expf(-v));
            out[(size_t)(m0 + g) * Ncols + tid] = v;
        }
    }
}

// ---------------- launch ----------------
extern "C" void kernel_launch(void* const* d_in, const int* in_sizes, int n_in,
                              void* d_out, int out_size) {
    const float* data = (const float*)d_in[0];
    const float* rois = (const float*)d_in[1];
    const float* w1   = (const float*)d_in[2];
    const float* b1   = (const float*)d_in[3];
    const float* w2   = (const float*)d_in[4];
    const float* b2   = (const float*)d_in[5];
    const float* w3   = (const float*)d_in[6];
    const float* b3   = (const float*)d_in[7];
    const float* wm1  = (const float*)d_in[8];
    const float* bm1  = (const float*)d_in[9];
    const float* wm2  = (const float*)d_in[10];
    const float* bm2  = (const float*)d_in[11];
    float* out = (float*)d_out;

    float *p_x, *p_part, *p_h1, *p_m1, *p_h2, *p_off, *p_mask;
    cudaGetSymbolAddress((void**)&p_x,    g_x);
    cudaGetSymbolAddress((void**)&p_part, g_part);
    cudaGetSymbolAddress((void**)&p_h1,   g_h1);
    cudaGetSymbolAddress((void**)&p_m1,   g_m1);
    cudaGetSymbolAddress((void**)&p_h2,   g_h2);
    cudaGetSymbolAddress((void**)&p_off,  g_off);
    cudaGetSymbolAddress((void**)&p_mask, g_mask);

    // 1. transpose data to channel-last
    transpose_kernel<<<dim3(HW/32, Cc/32, Bb), dim3(32, 8)>>>(data);

    // 2. pool1 (no offsets) -> g_x
    pool_kernel<false><<<dim3(Nroi, Pn), 128>>>(rois, nullptr, nullptr, p_x);

    // 3. fused big GEMM: x@w1 and x@wm1, split-K 4, 128 blocks
    gemm128<<<dim3(DF/128, Nroi/128, 8), 256>>>(p_x, INF, w1, wm1, DF, p_part, INF/4, 4);

    // 4. reduce + bias + relu -> h1, m1
    reduce1_kernel<<<(Nroi*DF)/256, 256>>>(b1, bm1);

    // 5. h1 @ w2, split-K 8
    gemm128<<<dim3(DF/128, Nroi/128, 8), 256>>>(p_h1, DF, w2, w2, DF, p_part, DF/8, 8);

    // 6. reduce + bias + relu -> h2
    reduce2_kernel<<<(Nroi*DF)/256, 256>>>(b2);

    // 7. offsets = h2 @ w3 + b3
    gemm_small<<<Nroi/8, 128>>>(p_h2, w3, b3, p_off, 2*Pn*Pn, 0);

    // 8. mask = sigmoid(m1 @ wm2 + bm2)
    gemm_small<<<Nroi/8, 128>>>(p_m1, wm2, bm2, p_mask, Pn*Pn, 1);

    // 9. pool2 with offsets, multiply mask -> out
    pool_kernel<true><<<dim3(Nroi, Pn), 128>>>(rois, p_off, p_mask, out);
}

// round 4
// speedup vs baseline: 1.1893x; 1.1893x over previous
#include <cuda_runtime.h>
#include <cuda_bf16.h>
#include <math.h>

#define Pn 7
#define Sn 4
#define SCALE 0.0625f
#define TRANS_STD 0.1f
#define Cc 128
#define DF 1024
#define Bb 2
#define Hh 160
#define Ww 160
#define Nroi 256
#define INF (Cc*Pn*Pn)   // 6272
#define HW (Hh*Ww)       // 25600

// ---------------- scratch (static device allocations; no cudaMalloc) ----------------
__device__ float g_dataT[Bb*HW*Cc];        // (B,H,W,C) transposed data
__device__ float g_x[Nroi*INF];            // pooled features, (N, C*P*P)
__device__ float g_part[16*Nroi*DF];       // split-K partials (16 z-slices of 256x1024)
__device__ float g_h1[Nroi*DF];
__device__ float g_m1[Nroi*DF];
__device__ float g_h2[Nroi*DF];
__device__ float g_off[Nroi*2*Pn*Pn];      // offsets (N,2,7,7)
__device__ float g_mask[Nroi*Pn*Pn];       // mask (N,7,7)

// ---------------- transpose (B,C,H,W) -> (B,H,W,C) ----------------
__global__ void transpose_kernel(const float* __restrict__ in) {
    __shared__ float tile[32][33];
    int b  = blockIdx.z;
    int p0 = blockIdx.x * 32;
    int c0 = blockIdx.y * 32;
    int tx = threadIdx.x, ty = threadIdx.y;
    const float* src = in + (size_t)b * Cc * HW;
    float* dst = g_dataT + (size_t)b * HW * Cc;
    #pragma unroll
    for (int i = 0; i < 4; i++)
        tile[ty + 8*i][tx] = src[(c0 + ty + 8*i) * HW + p0 + tx];
    __syncthreads();
    #pragma unroll
    for (int i = 0; i < 4; i++)
        dst[(p0 + ty + 8*i) * Cc + c0 + tx] = tile[tx][ty + 8*i];
}

// ---------------- deformable RoI pool ----------------
template<bool TRANS>
__global__ __launch_bounds__(128) void pool_kernel(
    const float* __restrict__ rois,
    const float* __restrict__ trans,   // (N,2,7,7) or null
    const float* __restrict__ mask,    // (N,7,7) or null
    float* __restrict__ out)
{
    int n  = blockIdx.x;
    int ph = blockIdx.y;
    int c  = threadIdx.x;

    const float* r = rois + n * 5;
    int   bi = (int)r[0];
    float x1 = rintf(r[1]) * SCALE - 0.5f;
    float y1 = rintf(r[2]) * SCALE - 0.5f;
    float x2 = (rintf(r[3]) + 1.0f) * SCALE - 0.5f;
    float y2 = (rintf(r[4]) + 1.0f) * SCALE - 0.5f;
    float roi_w = fmaxf(x2 - x1, 0.1f);
    float roi_h = fmaxf(y2 - y1, 0.1f);
    float bin_w = roi_w / (float)Pn;
    float bin_h = roi_h / (float)Pn;
    float sub_w = bin_w / (float)Sn;
    float sub_h = bin_h / (float)Sn;

    const float* base = g_dataT + (size_t)bi * HW * Cc;

    for (int pw = 0; pw < Pn; pw++) {
        float tx = 0.f, tyv = 0.f;
        if (TRANS) {
            tx  = trans[n*98 +      ph*7 + pw] * TRANS_STD;
            tyv = trans[n*98 + 49 + ph*7 + pw] * TRANS_STD;
        }
        float wst = (float)pw * bin_w + x1 + tx  * roi_w;
        float hst = (float)ph * bin_h + y1 + tyv * roi_h;

        float acc = 0.f;
        int cnt = 0;
        #pragma unroll
        for (int ih = 0; ih < Sn; ih++) {
            float hv = hst + (float)ih * sub_h;
            #pragma unroll
            for (int iw = 0; iw < Sn; iw++) {
                float wv = wst + (float)iw * sub_w;
                if (wv < -0.5f || wv > (float)Ww - 0.5f ||
                    hv < -0.5f || hv > (float)Hh - 0.5f) continue;
                float wc = fminf(fmaxf(wv, 0.f), (float)Ww - 1.f);
                float hc = fminf(fmaxf(hv, 0.f), (float)Hh - 1.f);
                int x0 = (int)floorf(wc);
                int y0 = (int)floorf(hc);
                int x1i = min(x0 + 1, Ww - 1);
                int y1i = min(y0 + 1, Hh - 1);
                float lx = wc - (float)x0;
                float ly = hc - (float)y0;
                const float* p00 = base + (y0  * Ww + x0 ) * Cc;
                const float* p01 = base + (y0  * Ww + x1i) * Cc;
                const float* p10 = base + (y1i * Ww + x0 ) * Cc;
                const float* p11 = base + (y1i * Ww + x1i) * Cc;
                float v = p00[c] * ((1.f-ly)*(1.f-lx))
                        + p01[c] * ((1.f-ly)*lx)
                        + p10[c] * (ly*(1.f-lx))
                        + p11[c] * (ly*lx);
                acc += v;
                cnt++;
            }
        }
        float res = (cnt > 0) ? acc / (float)cnt : 0.f;
        if (TRANS) res *= mask[n*49 + ph*7 + pw];
        out[n*INF + c*49 + ph*7 + pw] = res;   // (N,C,P,P) linearized
    }
}

// ---------------- big GEMM: 128x128 tile, f32x2 packed FMA, double-buffered ------
// grid: (DF/128, Nroi/128, z); z -> weight = z/kspl, kchunk = z%kspl
__global__ __launch_bounds__(256, 2) void gemm128(
    const float* __restrict__ A, int lda,
    const float* __restrict__ B0, const float* __restrict__ B1, int ldb,
    float* __restrict__ part, int klen, int kspl)
{
    __shared__ float As[2][8][128];
    __shared__ float Bs[2][8][128];

    int z = blockIdx.z;
    const float* B = (z / kspl == 0) ? B0 : B1;
    int kbase = (z % kspl) * klen;

    int tid = threadIdx.x;
    int a_r = tid >> 1;          // 0..127
    int a_c = (tid & 1) * 4;     // 0 or 4
    int b_r = tid >> 5;          // 0..7
    int b_c = (tid & 31) * 4;    // 0..124

    const float* Ap = A + (size_t)(blockIdx.y * 128 + a_r) * lda + kbase + a_c;
    const float* Bp = B + (size_t)(kbase + b_r) * ldb + blockIdx.x * 128 + b_c;

    int tx = tid & 15;           // 0..15
    int ty = tid >> 4;           // 0..15

    // packed accumulators: acc[i][p] holds 2 adjacent output columns
    unsigned long long acc[8][4];
    #pragma unroll
    for (int i = 0; i < 8; i++)
        #pragma unroll
        for (int p = 0; p < 4; p++) acc[i][p] = 0ULL;

    int stages = klen / 8;
    float4 pa = *(const float4*)Ap;
    float4 pb = *(const float4*)Bp;

    // stage 0 -> buffer 0
    As[0][a_c + 0][a_r] = pa.x;
    As[0][a_c + 1][a_r] = pa.y;
    As[0][a_c + 2][a_r] = pa.z;
    As[0][a_c + 3][a_r] = pa.w;
    *(float4*)&Bs[0][b_r][b_c] = pb;
    __syncthreads();

    int buf = 0;
    for (int s = 0; s < stages; s++) {
        if (s + 1 < stages) {
            Ap += 8;
            Bp += (size_t)8 * ldb;
            pa = *(const float4*)Ap;
            pb = *(const float4*)Bp;
        }

        #pragma unroll
        for (int kk = 0; kk < 8; kk++) {
            float4 a0 = *(const float4*)&As[buf][kk][ty * 4];
            float4 a1 = *(const float4*)&As[buf][kk][64 + ty * 4];
            ulonglong2 b01 = *(const ulonglong2*)&Bs[buf][kk][tx * 4];
            ulonglong2 b23 = *(const ulonglong2*)&Bs[buf][kk][64 + tx * 4];
            float av[8] = {a0.x, a0.y, a0.z, a0.w, a1.x, a1.y, a1.z, a1.w};
            #pragma unroll
            for (int i = 0; i < 8; i++) {
                unsigned long long a2;
                unsigned ai = __float_as_uint(av[i]);
                asm("mov.b64 %0, {%1, %1};" : "=l"(a2) : "r"(ai));
                asm("fma.rn.f32x2 %0, %1, %2, %0;" : "+l"(acc[i][0]) : "l"(a2), "l"(b01.x));
                asm("fma.rn.f32x2 %0, %1, %2, %0;" : "+l"(acc[i][1]) : "l"(a2), "l"(b01.y));
                asm("fma.rn.f32x2 %0, %1, %2, %0;" : "+l"(acc[i][2]) : "l"(a2), "l"(b23.x));
                asm("fma.rn.f32x2 %0, %1, %2, %0;" : "+l"(acc[i][3]) : "l"(a2), "l"(b23.y));
            }
        }

        if (s + 1 < stages) {
            int nb = buf ^ 1;
            As[nb][a_c + 0][a_r] = pa.x;
            As[nb][a_c + 1][a_r] = pa.y;
            As[nb][a_c + 2][a_r] = pa.z;
            As[nb][a_c + 3][a_r] = pa.w;
            *(float4*)&Bs[nb][b_r][b_c] = pb;
            __syncthreads();
            buf = nb;
        }
    }

    float* Cp = part + ((size_t)z * Nroi + blockIdx.y * 128) * DF + blockIdx.x * 128;
    #pragma unroll
    for (int i = 0; i < 8; i++) {
        int rr = (i < 4) ? (ty * 4 + i) : (64 + ty * 4 + i - 4);
        float o[8];
        #pragma unroll
        for (int p = 0; p < 4; p++) {
            unsigned lo, hi;
            asm("mov.b64 {%0, %1}, %2;" : "=r"(lo), "=r"(hi) : "l"(acc[i][p]));
            o[2*p]   = __uint_as_float(lo);
            o[2*p+1] = __uint_as_float(hi);
        }
        *(float4*)&Cp[(size_t)rr * DF + tx * 4]      = make_float4(o[0], o[1], o[2], o[3]);
        *(float4*)&Cp[(size_t)rr * DF + 64 + tx * 4] = make_float4(o[4], o[5], o[6], o[7]);
    }
}

// reduce 8 partials each for h1 (z=0..7, bias b1) and m1 (z=8..15, bias bm1), relu
__global__ void reduce1_kernel(const float* __restrict__ b1, const float* __restrict__ bm1) {
    int i4 = blockIdx.x * 256 + threadIdx.x;   // over 256*1024/4
    int base = i4 * 4;
    int n = base & (DF - 1);
    float4 s0 = *(const float4*)&b1[n];
    float4 s1 = *(const float4*)&bm1[n];
    #pragma unroll
    for (int c = 0; c < 8; c++) {
        float4 v = *(const float4*)&g_part[(size_t)c * (Nroi*DF) + base];
        s0.x += v.x; s0.y += v.y; s0.z += v.z; s0.w += v.w;
    }
    #pragma unroll
    for (int c = 8; c < 16; c++) {
        float4 v = *(const float4*)&g_part[(size_t)c * (Nroi*DF) + base];
        s1.x += v.x; s1.y += v.y; s1.z += v.z; s1.w += v.w;
    }
    *(float4*)&g_h1[base] = make_float4(fmaxf(s0.x,0.f), fmaxf(s0.y,0.f), fmaxf(s0.z,0.f), fmaxf(s0.w,0.f));
    *(float4*)&g_m1[base] = make_float4(fmaxf(s1.x,0.f), fmaxf(s1.y,0.f), fmaxf(s1.z,0.f), fmaxf(s1.w,0.f));
}

// reduce 16 partials for h2, bias b2, relu
__global__ void reduce2_kernel(const float* __restrict__ b2) {
    int i4 = blockIdx.x * 256 + threadIdx.x;
    int base = i4 * 4;
    int n = base & (DF - 1);
    float4 s = *(const float4*)&b2[n];
    #pragma unroll
    for (int c = 0; c < 16; c++) {
        float4 v = *(const float4*)&g_part[(size_t)c * (Nroi*DF) + base];
        s.x += v.x; s.y += v.y; s.z += v.z; s.w += v.w;
    }
    *(float4*)&g_h2[base] = make_float4(fmaxf(s.x,0.f), fmaxf(s.y,0.f), fmaxf(s.z,0.f), fmaxf(s.w,0.f));
}

// ---------------- small GEMM: (256,1024) @ (1024,Ncols) + bias [, sigmoid] -------
__global__ __launch_bounds__(128) void gemm_small(
    const float* __restrict__ A, const float* __restrict__ Wt,
    const float* __restrict__ bias, float* __restrict__ out,
    int Ncols, int act)
{
    __shared__ float arow[8][DF];
    int tid = threadIdx.x;
    int m0 = blockIdx.x * 8;
    #pragma unroll
    for (int g = 0; g < 8; g++)
        for (int k = tid; k < DF; k += 128)
            arow[g][k] = A[(size_t)(m0 + g) * DF + k];
    __syncthreads();

    if (tid < Ncols) {
        float bv = bias[tid];
        float acc[8];
        #pragma unroll
        for (int g = 0; g < 8; g++) acc[g] = bv;
        for (int k = 0; k < DF; k += 4) {
            float w0 = Wt[(size_t)(k + 0) * Ncols + tid];
            float w1 = Wt[(size_t)(k + 1) * Ncols + tid];
            float w2 = Wt[(size_t)(k + 2) * Ncols + tid];
            float w3 = Wt[(size_t)(k + 3) * Ncols + tid];
            #pragma unroll
            for (int g = 0; g < 8; g++) {
                float4 av = *(const float4*)&arow[g][k];
                acc[g] += av.x * w0 + av.y * w1 + av.z * w2 + av.w * w3;
            }
        }
        #pragma unroll
        for (int g = 0; g < 8; g++) {
            float v = acc[g];
            if (act) v = 1.f / (1.f + expf(-v));
            out[(size_t)(m0 + g) * Ncols + tid] = v;
        }
    }
}

// ---------------- launch ----------------
extern "C" void kernel_launch(void* const* d_in, const int* in_sizes, int n_in,
                              void* d_out, int out_size) {
    const float* data = (const float*)d_in[0];
    const float* rois = (const float*)d_in[1];
    const float* w1   = (const float*)d_in[2];
    const float* b1   = (const float*)d_in[3];
    const float* w2   = (const float*)d_in[4];
    const float* b2   = (const float*)d_in[5];
    const float* w3   = (const float*)d_in[6];
    const float* b3   = (const float*)d_in[7];
    const float* wm1  = (const float*)d_in[8];
    const float* bm1  = (const float*)d_in[9];
    const float* wm2  = (const float*)d_in[10];
    const float* bm2  = (const float*)d_in[11];
    float* out = (float*)d_out;

    float *p_x, *p_part, *p_h1, *p_m1, *p_h2, *p_off, *p_mask;
    cudaGetSymbolAddress((void**)&p_x,    g_x);
    cudaGetSymbolAddress((void**)&p_part, g_part);
    cudaGetSymbolAddress((void**)&p_h1,   g_h1);
    cudaGetSymbolAddress((void**)&p_m1,   g_m1);
    cudaGetSymbolAddress((void**)&p_h2,   g_h2);
    cudaGetSymbolAddress((void**)&p_off,  g_off);
    cudaGetSymbolAddress((void**)&p_mask, g_mask);

    // 1. transpose data to channel-last
    transpose_kernel<<<dim3(HW/32, Cc/32, Bb), dim3(32, 8)>>>(data);

    // 2. pool1 (no offsets) -> g_x
    pool_kernel<false><<<dim3(Nroi, Pn), 128>>>(rois, nullptr, nullptr, p_x);

    // 3. fused big GEMM: x@w1 (z=0..7) and x@wm1 (z=8..15), split-K 8 -> 256 blocks
    gemm128<<<dim3(DF/128, Nroi/128, 16), 256>>>(p_x, INF, w1, wm1, DF, p_part, INF/8, 8);

    // 4. reduce + bias + relu -> h1, m1
    reduce1_kernel<<<(Nroi*DF)/(256*4), 256>>>(b1, bm1);

    // 5. h1 @ w2, split-K 16 -> 256 blocks
    gemm128<<<dim3(DF/128, Nroi/128, 16), 256>>>(p_h1, DF, w2, w2, DF, p_part, DF/16, 16);

    // 6. reduce + bias + relu -> h2
    reduce2_kernel<<<(Nroi*DF)/(256*4), 256>>>(b2);

    // 7. offsets = h2 @ w3 + b3
    gemm_small<<<Nroi/8, 128>>>(p_h2, w3, b3, p_off, 2*Pn*Pn, 0);

    // 8. mask = sigmoid(m1 @ wm2 + bm2)
    gemm_small<<<Nroi/8, 128>>>(p_m1, wm2, bm2, p_mask, Pn*Pn, 1);

    // 9. pool2 with offsets, multiply mask -> out
    pool_kernel<true><<<dim3(Nroi, Pn), 128>>>(rois, p_off, p_mask, out);
}